// round 11
// baseline (speedup 1.0000x reference)
#include <cuda_runtime.h>
#include <cuda_fp16.h>
#include <cstdint>

// Problem constants  (V, E, H, B, T = 32000, 128, 256, 16, 256)
#define VSZ 32000
#define ESZ 128
#define HSZ 256
#define BSZ 16
#define TSZ 256
#define G4H 1024          // 4*H
#define MTOT 4096         // T*B

// ---------------- device scratch (no cudaMalloc allowed) ----------------
__device__ float    g_xproj0[MTOT * G4H];   // [T,B,4H]
__device__ float    g_h1s[MTOT * HSZ];      // [T,B,H]
__device__ float    g_hbuf[4 * BSZ * HSZ];  // L0 ping/pong, L1 ping/pong
__device__ unsigned g_bar[2];
// split-fp16 operands for the HMMA logits GEMM
__device__ __half g_whi[VSZ * HSZ];
__device__ __half g_wlo[VSZ * HSZ];
__device__ __half g_ah [MTOT * HSZ];        // fp16 A written by LSTM layer-1

// ---------------- helpers ----------------
#define FMA_F32X2(acc, a, b) \
    asm("fma.rn.f32x2 %0, %1, %2, %0;" : "+l"(acc) : "l"(a), "l"(b))

__device__ __forceinline__ unsigned long long pack_dup(float v) {
    unsigned long long r;
    asm("mov.b64 %0, {%1, %1};" : "=l"(r) : "f"(v));
    return r;
}
__device__ __forceinline__ unsigned long long pack2(float x, float y) {
    unsigned long long r;
    asm("mov.b64 %0, {%1, %2};" : "=l"(r) : "f"(x), "f"(y));
    return r;
}
__device__ __forceinline__ float lo32(unsigned long long v) {
    return __uint_as_float((unsigned)(v & 0xffffffffULL));
}
__device__ __forceinline__ float hi32(unsigned long long v) {
    return __uint_as_float((unsigned)(v >> 32));
}
__device__ __forceinline__ uint32_t smem_u32(const void* p) {
    uint32_t a;
    asm("{ .reg .u64 t; cvta.to.shared.u64 t, %1; cvt.u32.u64 %0, t; }"
        : "=r"(a) : "l"(p));
    return a;
}
__device__ __forceinline__ void cp16(uint32_t s, const void* g) {
    asm volatile("cp.async.cg.shared.global [%0], [%1], 16;"
                 :: "r"(s), "l"(g) : "memory");
}
__device__ __forceinline__ void ldm_x4(uint32_t* r, uint32_t addr) {
    asm volatile("ldmatrix.sync.aligned.m8n8.x4.shared.b16 {%0,%1,%2,%3}, [%4];"
                 : "=r"(r[0]), "=r"(r[1]), "=r"(r[2]), "=r"(r[3]) : "r"(addr));
}
__device__ __forceinline__ void mma_f16(float* d, const uint32_t* a, const uint32_t* b) {
    asm volatile(
        "mma.sync.aligned.m16n8k16.row.col.f32.f16.f16.f32 "
        "{%0,%1,%2,%3}, {%4,%5,%6,%7}, {%8,%9}, {%0,%1,%2,%3};"
        : "+f"(d[0]), "+f"(d[1]), "+f"(d[2]), "+f"(d[3])
        : "r"(a[0]), "r"(a[1]), "r"(a[2]), "r"(a[3]), "r"(b[0]), "r"(b[1]));
}
__device__ __forceinline__ unsigned ld_acq(const unsigned* p) {
    unsigned v;
    asm volatile("ld.acquire.gpu.global.u32 %0, [%1];" : "=r"(v) : "l"(p));
    return v;
}

// ---------------- init ----------------
__global__ void init_kernel() {
    int tid = blockIdx.x * blockDim.x + threadIdx.x;
    if (tid < 2) g_bar[tid] = 0u;
    for (int i = tid; i < 4 * BSZ * HSZ; i += gridDim.x * blockDim.x)
        g_hbuf[i] = 0.f;
}

// ---------------- split f32 -> fp16 hi + lo (weights) ----------------
__global__ void cvt_splith_kernel(const float* __restrict__ src,
                                  __half* __restrict__ hi,
                                  __half* __restrict__ lo, int n4) {
    int stride = gridDim.x * blockDim.x;
    const float4* s4 = (const float4*)src;
    unsigned long long* h8 = (unsigned long long*)hi;
    unsigned long long* l8 = (unsigned long long*)lo;
    for (int i = blockIdx.x * blockDim.x + threadIdx.x; i < n4; i += stride) {
        float4 v = s4[i];
        __half h0 = __float2half_rn(v.x);
        __half h1 = __float2half_rn(v.y);
        __half h2 = __float2half_rn(v.z);
        __half h3 = __float2half_rn(v.w);
        __half l0 = __float2half_rn(v.x - __half2float(h0));
        __half l1 = __float2half_rn(v.y - __half2float(h1));
        __half l2 = __float2half_rn(v.z - __half2float(h2));
        __half l3 = __float2half_rn(v.w - __half2float(h3));
        unsigned long long ph =
            (unsigned long long)__half_as_ushort(h0) |
            ((unsigned long long)__half_as_ushort(h1) << 16) |
            ((unsigned long long)__half_as_ushort(h2) << 32) |
            ((unsigned long long)__half_as_ushort(h3) << 48);
        unsigned long long pl =
            (unsigned long long)__half_as_ushort(l0) |
            ((unsigned long long)__half_as_ushort(l1) << 16) |
            ((unsigned long long)__half_as_ushort(l2) << 32) |
            ((unsigned long long)__half_as_ushort(l3) << 48);
        h8[i] = ph;
        l8[i] = pl;
    }
}

// ---------------- SGEMM (x-proj layer 0) ----------------
template <int MODE>
__global__ __launch_bounds__(256) void sgemm_kernel(
    const float* __restrict__ A, const int* __restrict__ gidx,
    const float* __restrict__ Wt, const float* __restrict__ bias1,
    const float* __restrict__ bias2, float* __restrict__ C,
    int M, int N, int K)
{
    __shared__ float As[16][128];
    __shared__ float Bs[16][128];

    const int tid = threadIdx.x;
    const int n0 = blockIdx.x * 128;
    const int m0 = blockIdx.y * 128;

    const int lr = tid >> 2;
    const int lc = (tid & 3) << 2;

    const float* ap0;
    const float* ap1;
    {
        int mA0 = m0 + lr, mA1 = m0 + lr + 64;
        if (MODE == 0) {
            int t0 = mA0 >> 4, b0 = mA0 & 15;
            int t1 = mA1 >> 4, b1 = mA1 & 15;
            ap0 = A + (long)gidx[b0 * TSZ + t0] * K;
            ap1 = A + (long)gidx[b1 * TSZ + t1] * K;
        } else {
            ap0 = A + (long)mA0 * K;
            ap1 = A + (long)mA1 * K;
        }
    }
    const float* bp0 = Wt + (long)(n0 + lr) * K;
    const float* bp1 = Wt + (long)(n0 + lr + 64) * K;

    const int ty = tid >> 4, tx = tid & 15;
    const int row = ty << 3, col = tx << 3;

    unsigned long long acc[8][4];
#pragma unroll
    for (int i = 0; i < 8; i++)
#pragma unroll
        for (int j = 0; j < 4; j++) acc[i][j] = 0ULL;

    for (int kt = 0; kt < K; kt += 16) {
        float4 a0 = *(const float4*)(ap0 + kt + lc);
        float4 a1 = *(const float4*)(ap1 + kt + lc);
        float4 w0 = *(const float4*)(bp0 + kt + lc);
        float4 w1 = *(const float4*)(bp1 + kt + lc);
        __syncthreads();
        As[lc + 0][lr] = a0.x; As[lc + 1][lr] = a0.y;
        As[lc + 2][lr] = a0.z; As[lc + 3][lr] = a0.w;
        As[lc + 0][lr + 64] = a1.x; As[lc + 1][lr + 64] = a1.y;
        As[lc + 2][lr + 64] = a1.z; As[lc + 3][lr + 64] = a1.w;
        Bs[lc + 0][lr] = w0.x; Bs[lc + 1][lr] = w0.y;
        Bs[lc + 2][lr] = w0.z; Bs[lc + 3][lr] = w0.w;
        Bs[lc + 0][lr + 64] = w1.x; Bs[lc + 1][lr + 64] = w1.y;
        Bs[lc + 2][lr + 64] = w1.z; Bs[lc + 3][lr + 64] = w1.w;
        __syncthreads();

#pragma unroll
        for (int k = 0; k < 16; k++) {
            float4 av0 = *(const float4*)&As[k][row];
            float4 av1 = *(const float4*)&As[k][row + 4];
            float4 bq0 = *(const float4*)&Bs[k][col];
            float4 bq1 = *(const float4*)&Bs[k][col + 4];
            unsigned long long bv0 = pack2(bq0.x, bq0.y);
            unsigned long long bv1 = pack2(bq0.z, bq0.w);
            unsigned long long bv2 = pack2(bq1.x, bq1.y);
            unsigned long long bv3 = pack2(bq1.z, bq1.w);
            float av[8] = {av0.x, av0.y, av0.z, av0.w, av1.x, av1.y, av1.z, av1.w};
#pragma unroll
            for (int i = 0; i < 8; i++) {
                unsigned long long a2 = pack_dup(av[i]);
                FMA_F32X2(acc[i][0], a2, bv0);
                FMA_F32X2(acc[i][1], a2, bv1);
                FMA_F32X2(acc[i][2], a2, bv2);
                FMA_F32X2(acc[i][3], a2, bv3);
            }
        }
    }

#pragma unroll
    for (int i = 0; i < 8; i++) {
        int m = m0 + row + i;
        long base = (long)m * N;
#pragma unroll
        for (int j = 0; j < 4; j++) {
            int n = n0 + col + 2 * j;
            float b0 = bias1[n] + (bias2 ? bias2[n] : 0.f);
            float b1 = bias1[n + 1] + (bias2 ? bias2[n + 1] : 0.f);
            C[base + n] = lo32(acc[i][j]) + b0;
            C[base + n + 1] = hi32(acc[i][j]) + b1;
        }
    }
}

// ================= MEGA KERNEL: fused LSTM wavefront + overlapped logits ====
// grid = 8128.  bid<64: LSTM L0.  64<=bid<128: LSTM L1 (writes g_ah fp16).
// bid>=128: logits fp16 HMMA CTA (2-term split-W), waits on bar1 per m-tile.
// Dyn smem 98816B:
//   LSTM:   Ws2[4096] Wi2[4096] hs_s[4096] xs_s[4096] gbuf[272] (floats)
//   logits: stage s @ s*49152: Ah(16K) Whi(16K) Wlo(16K); bias @ 98304 (128 f)
#define MEGA_SMEM 98816
__global__ __launch_bounds__(256, 2) void mega_kernel(
    const float* __restrict__ xproj0, const float* __restrict__ W_hh0,
    const float* __restrict__ W_ih1, const float* __restrict__ W_hh1,
    const float* __restrict__ b_ih1, const float* __restrict__ b_hh1,
    float* __restrict__ hbuf, float* __restrict__ h1s,
    __half* __restrict__ ah,
    const __half* __restrict__ Whi, const __half* __restrict__ Wlo,
    const float* __restrict__ bias, float* __restrict__ out,
    float* __restrict__ hf0, float* __restrict__ cf0,
    float* __restrict__ hf1, float* __restrict__ cf1,
    unsigned* __restrict__ bars)
{
    extern __shared__ float sm[];
    const int tid = threadIdx.x;

    if (blockIdx.x < 128) {
        // ================= LSTM wavefront =================
        float* Ws2  = sm;
        float* Wi2  = sm + 4096;
        float* hs_s = sm + 8192;
        float* xs_s = sm + 12288;
        float* gbuf = sm + 16384;

        const bool L1k = (blockIdx.x >= 64);
        const int cta = L1k ? blockIdx.x - 64 : blockIdx.x;
        const int j0 = cta * 4;

        const float* Whh = L1k ? W_hh1 : W_hh0;
        for (int idx = tid; idx < 16 * HSZ; idx += 256) {
            int k = idx >> 4, r = idx & 15;
            int g = r >> 2, jj = r & 3;
            int wrow = (g * HSZ + j0 + jj) * HSZ + k;
            int soff = (k >> 1) * 32 + r * 2 + (k & 1);
            Ws2[soff] = Whh[wrow];
            if (L1k) Wi2[soff] = W_ih1[wrow];
        }
        __syncthreads();

        const int b = tid >> 4, r = tid & 15;
        const int gcol = (r >> 2) * HSZ + j0 + (r & 3);
        const int ub = tid >> 2, ujj = tid & 3;
        const float biasv = L1k ? (b_ih1[gcol] + b_hh1[gcol]) : 0.f;

        float* base = hbuf + (L1k ? 2 * BSZ * HSZ : 0);
        float* pp[2] = {base, base + BSZ * HSZ};
        float* hfin = L1k ? hf1 : hf0;
        float* cfin = L1k ? cf1 : cf0;

        float c_st = 0.f, h_st = 0.f;

        for (int t = 0; t < TSZ; t++) {
            if (tid == 0) {
                unsigned w0 = L1k ? 64u * (t + 1) : 64u * t;
                while (ld_acq(&bars[0]) < w0) {}
                if (L1k && t > 0) {
                    unsigned w1 = 64u * t;
                    while (ld_acq(&bars[1]) < w1) {}
                }
            }
            __syncthreads();

            {
                const float4* src = (const float4*)pp[t & 1];
                float4* dst = (float4*)hs_s;
#pragma unroll
                for (int j = 0; j < 4; j++)
                    dst[tid + 256 * j] = __ldcg(src + tid + 256 * j);
                if (L1k) {
                    const float4* xsrc = (const float4*)(h1s + (size_t)t * BSZ * HSZ);
                    float4* xdst = (float4*)xs_s;
#pragma unroll
                    for (int j = 0; j < 4; j++)
                        xdst[tid + 256 * j] = __ldcg(xsrc + tid + 256 * j);
                }
            }
            __syncthreads();

            unsigned long long accA = 0ULL, accB = 0ULL;
            const unsigned long long* hrow = (const unsigned long long*)(hs_s + b * HSZ);
#pragma unroll 16
            for (int k2 = 0; k2 < 128; k2 += 2) {
                unsigned long long h0 = hrow[k2];
                unsigned long long h1v = hrow[k2 + 1];
                unsigned long long w0 = *(const unsigned long long*)&Ws2[k2 * 32 + r * 2];
                unsigned long long w1 = *(const unsigned long long*)&Ws2[(k2 + 1) * 32 + r * 2];
                FMA_F32X2(accA, h0, w0);
                FMA_F32X2(accB, h1v, w1);
            }
            float acc = (lo32(accA) + hi32(accA)) + (lo32(accB) + hi32(accB));
            if (L1k) {
                unsigned long long accC = 0ULL, accD = 0ULL;
                const unsigned long long* xrow = (const unsigned long long*)(xs_s + b * HSZ);
#pragma unroll 16
                for (int k2 = 0; k2 < 128; k2 += 2) {
                    unsigned long long x0 = xrow[k2];
                    unsigned long long x1 = xrow[k2 + 1];
                    unsigned long long w0 = *(const unsigned long long*)&Wi2[k2 * 32 + r * 2];
                    unsigned long long w1 = *(const unsigned long long*)&Wi2[(k2 + 1) * 32 + r * 2];
                    FMA_F32X2(accC, x0, w0);
                    FMA_F32X2(accD, x1, w1);
                }
                acc += (lo32(accC) + hi32(accC)) + (lo32(accD) + hi32(accD)) + biasv;
            } else {
                acc += xproj0[((size_t)t * BSZ + b) * G4H + gcol];
            }
            gbuf[b * 17 + r] = acc;
            __syncthreads();

            if (tid < 64) {
                float iv = gbuf[ub * 17 + ujj];
                float fv = gbuf[ub * 17 + 4 + ujj];
                float gv = gbuf[ub * 17 + 8 + ujj];
                float ov = gbuf[ub * 17 + 12 + ujj];
                iv = 1.f / (1.f + expf(-iv));
                fv = 1.f / (1.f + expf(-fv));
                ov = 1.f / (1.f + expf(-ov));
                gv = tanhf(gv);
                c_st = fv * c_st + iv * gv;
                h_st = ov * tanhf(c_st);
                int hcol = j0 + ujj;
                __stcg(&pp[(t + 1) & 1][ub * HSZ + hcol], h_st);
                if (L1k) {
                    // emit fp16 A row for the logits GEMM
                    ah[((size_t)t * BSZ + ub) * HSZ + hcol] = __float2half_rn(h_st);
                } else {
                    __stcg(&h1s[((size_t)t * BSZ + ub) * HSZ + hcol], h_st);
                }
            }
            __syncthreads();

            if (tid == 0) {
                unsigned* bar = &bars[L1k ? 1 : 0];
                asm volatile("red.release.gpu.global.add.u32 [%0], 1;" :: "l"(bar) : "memory");
            }
            __syncthreads();
        }

        if (tid < 64) {
            hfin[ub * HSZ + j0 + ujj] = h_st;
            cfin[ub * HSZ + j0 + ujj] = c_st;
        }
    } else {
        // ================= logits fp16 HMMA (2-term, split W) =================
        const int idx = blockIdx.x - 128;
        const int my = idx / 250, nx = idx - my * 250;
        const int m0 = my * 128, n0 = nx * 128;
        const int lane = tid & 31, w = tid >> 5;
        const int wm = w >> 1, wn = w & 1;
        const uint32_t sb = smem_u32(sm);
        float* sbias = sm + 24576;   // 98304 bytes / 4

        // wait for layer-1 to finish timestep 8*my+7 (A rows m0..m0+127)
        if (tid == 0) {
            unsigned need = 512u * (my + 1);
            while (ld_acq(&bars[1]) < need) {}
        }
        if (tid < 128) sbias[tid] = bias[n0 + tid];
        __syncthreads();

        auto issue = [&](int c, int s) {
            uint32_t st = sb + s * 49152;
#pragma unroll
            for (int i = 0; i < 4; i++) {
                int lin = tid + i * 256;
                int row = lin >> 3, ch = lin & 7;
                uint32_t phys = row * 128 + ((ch ^ (row & 7)) << 4);
                size_t ga = (size_t)(m0 + row) * HSZ + c * 64 + ch * 8;
                size_t gb = (size_t)(n0 + row) * HSZ + c * 64 + ch * 8;
                cp16(st + phys,         ah + ga);
                cp16(st + 16384 + phys, Whi + gb);
                cp16(st + 32768 + phys, Wlo + gb);
            }
            asm volatile("cp.async.commit_group;" ::: "memory");
        };

        float d[2][8][4];
#pragma unroll
        for (int mt = 0; mt < 2; mt++)
#pragma unroll
            for (int nt = 0; nt < 8; nt++)
#pragma unroll
                for (int j = 0; j < 4; j++) d[mt][nt][j] = 0.f;

        issue(0, 0);

        for (int c = 0; c < 4; c++) {
            const int s = c & 1;
            if (c < 3) {
                issue(c + 1, s ^ 1);
                asm volatile("cp.async.wait_group 1;" ::: "memory");
            } else {
                asm volatile("cp.async.wait_group 0;" ::: "memory");
            }
            __syncthreads();

            const uint32_t st = sb + s * 49152;
#pragma unroll
            for (int ks = 0; ks < 4; ks++) {
                uint32_t ahf[2][4];
#pragma unroll
                for (int mt = 0; mt < 2; mt++) {
                    int row = wm * 32 + mt * 16 + (lane & 7) + ((lane >> 3) & 1) * 8;
                    int ch = ks * 2 + ((lane >> 4) & 1);
                    ldm_x4(ahf[mt], st + row * 128 + ((ch ^ (row & 7)) << 4));
                }
#pragma unroll
                for (int nt2 = 0; nt2 < 4; nt2++) {
                    int row = wn * 64 + nt2 * 16 + (lane & 7) + ((lane >> 4) & 1) * 8;
                    int ch = ks * 2 + ((lane >> 3) & 1);
                    uint32_t ad = st + 16384 + row * 128 + ((ch ^ (row & 7)) << 4);
                    uint32_t qh[4], ql[4];
                    ldm_x4(qh, ad);
                    ldm_x4(ql, ad + 16384);
#pragma unroll
                    for (int mt = 0; mt < 2; mt++) {
                        mma_f16(d[mt][2 * nt2],     ahf[mt], qh);
                        mma_f16(d[mt][2 * nt2],     ahf[mt], ql);
                        mma_f16(d[mt][2 * nt2 + 1], ahf[mt], qh + 2);
                        mma_f16(d[mt][2 * nt2 + 1], ahf[mt], ql + 2);
                    }
                }
            }
            __syncthreads();
        }

        // epilogue: bias + [t,b]->[b,t] remapped store
#pragma unroll
        for (int mt = 0; mt < 2; mt++) {
            int mrow = m0 + wm * 32 + mt * 16 + (lane >> 2);
#pragma unroll
            for (int half = 0; half < 2; half++) {
                int m = mrow + half * 8;
                int t = m >> 4, b = m & 15;
                float* dst = out + ((long)b * TSZ + t) * (long)VSZ + n0;
#pragma unroll
                for (int nt = 0; nt < 8; nt++) {
                    int lc = wn * 64 + nt * 8 + (lane & 3) * 2;
                    float2 v;
                    v.x = d[mt][nt][half * 2 + 0] + sbias[lc];
                    v.y = d[mt][nt][half * 2 + 1] + sbias[lc + 1];
                    *(float2*)(dst + lc) = v;
                }
            }
        }
    }
}

// ---------------- launch ----------------
extern "C" void kernel_launch(void* const* d_in, const int* in_sizes, int n_in,
                              void* d_out, int out_size) {
    const int*   x     = (const int*)d_in[0];
    const float* emb   = (const float*)d_in[1];
    const float* W_ih0 = (const float*)d_in[2];
    const float* W_hh0 = (const float*)d_in[3];
    const float* b_ih0 = (const float*)d_in[4];
    const float* b_hh0 = (const float*)d_in[5];
    const float* W_ih1 = (const float*)d_in[6];
    const float* W_hh1 = (const float*)d_in[7];
    const float* b_ih1 = (const float*)d_in[8];
    const float* b_hh1 = (const float*)d_in[9];
    const float* W_fc  = (const float*)d_in[10];
    const float* b_fc  = (const float*)d_in[11];
    float* out = (float*)d_out;

    float *xp0, *h1s, *hb;
    unsigned* bars;
    __half *whi, *wlo, *ah;
    cudaGetSymbolAddress((void**)&xp0,  g_xproj0);
    cudaGetSymbolAddress((void**)&h1s,  g_h1s);
    cudaGetSymbolAddress((void**)&hb,   g_hbuf);
    cudaGetSymbolAddress((void**)&bars, g_bar);
    cudaGetSymbolAddress((void**)&whi,  g_whi);
    cudaGetSymbolAddress((void**)&wlo,  g_wlo);
    cudaGetSymbolAddress((void**)&ah,   g_ah);

    cudaFuncSetAttribute(mega_kernel,
                         cudaFuncAttributeMaxDynamicSharedMemorySize, MEGA_SMEM);

    const long OFF_H = (long)BSZ * TSZ * VSZ;           // logits size
    const long OFF_C = OFF_H + 2L * BSZ * HSZ;
    const bool ws = ((long)out_size >= OFF_C + 2L * BSZ * HSZ);
    float* hf0 = ws ? out + OFF_H : nullptr;
    float* hf1 = ws ? out + OFF_H + BSZ * HSZ : nullptr;
    float* cf0 = ws ? out + OFF_C : nullptr;
    float* cf1 = ws ? out + OFF_C + BSZ * HSZ : nullptr;
    if (!ws) { hf0 = hb; hf1 = hb; cf0 = hb; cf1 = hb; }

    init_kernel<<<8, 256>>>();
    cvt_splith_kernel<<<2048, 256>>>(W_fc, whi, wlo, VSZ * HSZ / 4);

    dim3 gproj(G4H / 128, MTOT / 128);   // (8, 32)
    sgemm_kernel<0><<<gproj, 256>>>(emb, x, W_ih0, b_ih0, b_hh0, xp0,
                                    MTOT, G4H, ESZ);

    mega_kernel<<<128 + (VSZ / 128) * (MTOT / 128), 256, MEGA_SMEM>>>(
        xp0, W_hh0, W_ih1, W_hh1, b_ih1, b_hh1,
        hb, h1s, ah, whi, wlo, b_fc, out,
        hf0, cf0, hf1, cf1, bars);
}

// round 14
// speedup vs baseline: 1.0638x; 1.0638x over previous
#include <cuda_runtime.h>
#include <cuda_fp16.h>
#include <cstdint>

// Problem constants  (V, E, H, B, T = 32000, 128, 256, 16, 256)
#define VSZ 32000
#define ESZ 128
#define HSZ 256
#define BSZ 16
#define TSZ 256
#define G4H 1024          // 4*H
#define MTOT 4096         // T*B

// ---------------- device scratch (no cudaMalloc allowed) ----------------
__device__ float    g_xproj0[MTOT * G4H];   // [T,B,4H]
__device__ float    g_h1s[MTOT * HSZ];      // [T,B,H]
__device__ float    g_hbuf[4 * BSZ * HSZ];  // L0 ping/pong, L1 ping/pong
__device__ unsigned g_bar[2];
// split-fp16 operands for the HMMA logits GEMM
__device__ __half g_whi[VSZ * HSZ];
__device__ __half g_wlo[VSZ * HSZ];
__device__ __half g_ah [MTOT * HSZ];        // fp16 A written by LSTM layer-1

// ---------------- helpers ----------------
#define FMA_F32X2(acc, a, b) \
    asm("fma.rn.f32x2 %0, %1, %2, %0;" : "+l"(acc) : "l"(a), "l"(b))

__device__ __forceinline__ unsigned long long pack_dup(float v) {
    unsigned long long r;
    asm("mov.b64 %0, {%1, %1};" : "=l"(r) : "f"(v));
    return r;
}
__device__ __forceinline__ unsigned long long pack2(float x, float y) {
    unsigned long long r;
    asm("mov.b64 %0, {%1, %2};" : "=l"(r) : "f"(x), "f"(y));
    return r;
}
__device__ __forceinline__ float lo32(unsigned long long v) {
    return __uint_as_float((unsigned)(v & 0xffffffffULL));
}
__device__ __forceinline__ float hi32(unsigned long long v) {
    return __uint_as_float((unsigned)(v >> 32));
}
__device__ __forceinline__ uint32_t smem_u32(const void* p) {
    uint32_t a;
    asm("{ .reg .u64 t; cvta.to.shared.u64 t, %1; cvt.u32.u64 %0, t; }"
        : "=r"(a) : "l"(p));
    return a;
}
__device__ __forceinline__ void cp16(uint32_t s, const void* g) {
    asm volatile("cp.async.cg.shared.global [%0], [%1], 16;"
                 :: "r"(s), "l"(g) : "memory");
}
__device__ __forceinline__ void ldm_x4(uint32_t* r, uint32_t addr) {
    asm volatile("ldmatrix.sync.aligned.m8n8.x4.shared.b16 {%0,%1,%2,%3}, [%4];"
                 : "=r"(r[0]), "=r"(r[1]), "=r"(r[2]), "=r"(r[3]) : "r"(addr));
}
__device__ __forceinline__ void mma_f16(float* d, const uint32_t* a, const uint32_t* b) {
    asm volatile(
        "mma.sync.aligned.m16n8k16.row.col.f32.f16.f16.f32 "
        "{%0,%1,%2,%3}, {%4,%5,%6,%7}, {%8,%9}, {%0,%1,%2,%3};"
        : "+f"(d[0]), "+f"(d[1]), "+f"(d[2]), "+f"(d[3])
        : "r"(a[0]), "r"(a[1]), "r"(a[2]), "r"(a[3]), "r"(b[0]), "r"(b[1]));
}
__device__ __forceinline__ unsigned ld_acq(const unsigned* p) {
    unsigned v;
    asm volatile("ld.acquire.gpu.global.u32 %0, [%1];" : "=r"(v) : "l"(p));
    return v;
}

// ---------------- init ----------------
__global__ void init_kernel() {
    int tid = blockIdx.x * blockDim.x + threadIdx.x;
    if (tid < 2) g_bar[tid] = 0u;
    for (int i = tid; i < 4 * BSZ * HSZ; i += gridDim.x * blockDim.x)
        g_hbuf[i] = 0.f;
}

// ---------------- split f32 -> fp16 hi + lo (weights) ----------------
__global__ void cvt_splith_kernel(const float* __restrict__ src,
                                  __half* __restrict__ hi,
                                  __half* __restrict__ lo, int n4) {
    int stride = gridDim.x * blockDim.x;
    const float4* s4 = (const float4*)src;
    unsigned long long* h8 = (unsigned long long*)hi;
    unsigned long long* l8 = (unsigned long long*)lo;
    for (int i = blockIdx.x * blockDim.x + threadIdx.x; i < n4; i += stride) {
        float4 v = s4[i];
        __half h0 = __float2half_rn(v.x);
        __half h1 = __float2half_rn(v.y);
        __half h2 = __float2half_rn(v.z);
        __half h3 = __float2half_rn(v.w);
        __half l0 = __float2half_rn(v.x - __half2float(h0));
        __half l1 = __float2half_rn(v.y - __half2float(h1));
        __half l2 = __float2half_rn(v.z - __half2float(h2));
        __half l3 = __float2half_rn(v.w - __half2float(h3));
        unsigned long long ph =
            (unsigned long long)__half_as_ushort(h0) |
            ((unsigned long long)__half_as_ushort(h1) << 16) |
            ((unsigned long long)__half_as_ushort(h2) << 32) |
            ((unsigned long long)__half_as_ushort(h3) << 48);
        unsigned long long pl =
            (unsigned long long)__half_as_ushort(l0) |
            ((unsigned long long)__half_as_ushort(l1) << 16) |
            ((unsigned long long)__half_as_ushort(l2) << 32) |
            ((unsigned long long)__half_as_ushort(l3) << 48);
        h8[i] = ph;
        l8[i] = pl;
    }
}

// ---------------- SGEMM (x-proj layer 0) ----------------
template <int MODE>
__global__ __launch_bounds__(256) void sgemm_kernel(
    const float* __restrict__ A, const int* __restrict__ gidx,
    const float* __restrict__ Wt, const float* __restrict__ bias1,
    const float* __restrict__ bias2, float* __restrict__ C,
    int M, int N, int K)
{
    __shared__ float As[16][128];
    __shared__ float Bs[16][128];

    const int tid = threadIdx.x;
    const int n0 = blockIdx.x * 128;
    const int m0 = blockIdx.y * 128;

    const int lr = tid >> 2;
    const int lc = (tid & 3) << 2;

    const float* ap0;
    const float* ap1;
    {
        int mA0 = m0 + lr, mA1 = m0 + lr + 64;
        if (MODE == 0) {
            int t0 = mA0 >> 4, b0 = mA0 & 15;
            int t1 = mA1 >> 4, b1 = mA1 & 15;
            ap0 = A + (long)gidx[b0 * TSZ + t0] * K;
            ap1 = A + (long)gidx[b1 * TSZ + t1] * K;
        } else {
            ap0 = A + (long)mA0 * K;
            ap1 = A + (long)mA1 * K;
        }
    }
    const float* bp0 = Wt + (long)(n0 + lr) * K;
    const float* bp1 = Wt + (long)(n0 + lr + 64) * K;

    const int ty = tid >> 4, tx = tid & 15;
    const int row = ty << 3, col = tx << 3;

    unsigned long long acc[8][4];
#pragma unroll
    for (int i = 0; i < 8; i++)
#pragma unroll
        for (int j = 0; j < 4; j++) acc[i][j] = 0ULL;

    for (int kt = 0; kt < K; kt += 16) {
        float4 a0 = *(const float4*)(ap0 + kt + lc);
        float4 a1 = *(const float4*)(ap1 + kt + lc);
        float4 w0 = *(const float4*)(bp0 + kt + lc);
        float4 w1 = *(const float4*)(bp1 + kt + lc);
        __syncthreads();
        As[lc + 0][lr] = a0.x; As[lc + 1][lr] = a0.y;
        As[lc + 2][lr] = a0.z; As[lc + 3][lr] = a0.w;
        As[lc + 0][lr + 64] = a1.x; As[lc + 1][lr + 64] = a1.y;
        As[lc + 2][lr + 64] = a1.z; As[lc + 3][lr + 64] = a1.w;
        Bs[lc + 0][lr] = w0.x; Bs[lc + 1][lr] = w0.y;
        Bs[lc + 2][lr] = w0.z; Bs[lc + 3][lr] = w0.w;
        Bs[lc + 0][lr + 64] = w1.x; Bs[lc + 1][lr + 64] = w1.y;
        Bs[lc + 2][lr + 64] = w1.z; Bs[lc + 3][lr + 64] = w1.w;
        __syncthreads();

#pragma unroll
        for (int k = 0; k < 16; k++) {
            float4 av0 = *(const float4*)&As[k][row];
            float4 av1 = *(const float4*)&As[k][row + 4];
            float4 bq0 = *(const float4*)&Bs[k][col];
            float4 bq1 = *(const float4*)&Bs[k][col + 4];
            unsigned long long bv0 = pack2(bq0.x, bq0.y);
            unsigned long long bv1 = pack2(bq0.z, bq0.w);
            unsigned long long bv2 = pack2(bq1.x, bq1.y);
            unsigned long long bv3 = pack2(bq1.z, bq1.w);
            float av[8] = {av0.x, av0.y, av0.z, av0.w, av1.x, av1.y, av1.z, av1.w};
#pragma unroll
            for (int i = 0; i < 8; i++) {
                unsigned long long a2 = pack_dup(av[i]);
                FMA_F32X2(acc[i][0], a2, bv0);
                FMA_F32X2(acc[i][1], a2, bv1);
                FMA_F32X2(acc[i][2], a2, bv2);
                FMA_F32X2(acc[i][3], a2, bv3);
            }
        }
    }

#pragma unroll
    for (int i = 0; i < 8; i++) {
        int m = m0 + row + i;
        long base = (long)m * N;
#pragma unroll
        for (int j = 0; j < 4; j++) {
            int n = n0 + col + 2 * j;
            float b0 = bias1[n] + (bias2 ? bias2[n] : 0.f);
            float b1 = bias1[n + 1] + (bias2 ? bias2[n + 1] : 0.f);
            C[base + n] = lo32(acc[i][j]) + b0;
            C[base + n + 1] = hi32(acc[i][j]) + b1;
        }
    }
}

// ---------------- fused wavefront 2-layer LSTM (standalone, 128 CTAs) ------
// CTA<64: layer 0 (xproj0 precomputed). CTA>=64: layer 1, one step behind,
// input projection on the fly; emits A as fp16 (g_ah). No co-resident logits
// CTAs -> latency chain runs clean.
#define FUSED_SMEM ((16384 + 272) * 4)
__global__ __launch_bounds__(256, 1) void fused_lstm_kernel(
    const float* __restrict__ xproj0, const float* __restrict__ W_hh0,
    const float* __restrict__ W_ih1, const float* __restrict__ W_hh1,
    const float* __restrict__ b_ih1, const float* __restrict__ b_hh1,
    float* __restrict__ hbuf, float* __restrict__ h1s,
    __half* __restrict__ ah,
    float* __restrict__ hf0, float* __restrict__ cf0,
    float* __restrict__ hf1, float* __restrict__ cf1,
    unsigned* __restrict__ bars)
{
    extern __shared__ float sm[];
    float* Ws2  = sm;
    float* Wi2  = sm + 4096;
    float* hs_s = sm + 8192;
    float* xs_s = sm + 12288;
    float* gbuf = sm + 16384;

    const int tid = threadIdx.x;
    const bool L1k = (blockIdx.x >= 64);
    const int cta = L1k ? blockIdx.x - 64 : blockIdx.x;
    const int j0 = cta * 4;

    const float* Whh = L1k ? W_hh1 : W_hh0;
    for (int idx = tid; idx < 16 * HSZ; idx += 256) {
        int k = idx >> 4, r = idx & 15;
        int g = r >> 2, jj = r & 3;
        int wrow = (g * HSZ + j0 + jj) * HSZ + k;
        int soff = (k >> 1) * 32 + r * 2 + (k & 1);
        Ws2[soff] = Whh[wrow];
        if (L1k) Wi2[soff] = W_ih1[wrow];
    }
    __syncthreads();

    const int b = tid >> 4, r = tid & 15;
    const int gcol = (r >> 2) * HSZ + j0 + (r & 3);
    const int ub = tid >> 2, ujj = tid & 3;
    const float biasv = L1k ? (b_ih1[gcol] + b_hh1[gcol]) : 0.f;

    float* base = hbuf + (L1k ? 2 * BSZ * HSZ : 0);
    float* pp[2] = {base, base + BSZ * HSZ};
    float* hfin = L1k ? hf1 : hf0;
    float* cfin = L1k ? cf1 : cf0;

    float c_st = 0.f, h_st = 0.f;

    for (int t = 0; t < TSZ; t++) {
        if (tid == 0) {
            unsigned w0 = L1k ? 64u * (t + 1) : 64u * t;
            while (ld_acq(&bars[0]) < w0) {}
            if (L1k && t > 0) {
                unsigned w1 = 64u * t;
                while (ld_acq(&bars[1]) < w1) {}
            }
        }
        __syncthreads();

        {
            const float4* src = (const float4*)pp[t & 1];
            float4* dst = (float4*)hs_s;
#pragma unroll
            for (int j = 0; j < 4; j++)
                dst[tid + 256 * j] = __ldcg(src + tid + 256 * j);
            if (L1k) {
                const float4* xsrc = (const float4*)(h1s + (size_t)t * BSZ * HSZ);
                float4* xdst = (float4*)xs_s;
#pragma unroll
                for (int j = 0; j < 4; j++)
                    xdst[tid + 256 * j] = __ldcg(xsrc + tid + 256 * j);
            }
        }
        __syncthreads();

        unsigned long long accA = 0ULL, accB = 0ULL;
        const unsigned long long* hrow = (const unsigned long long*)(hs_s + b * HSZ);
#pragma unroll 16
        for (int k2 = 0; k2 < 128; k2 += 2) {
            unsigned long long h0 = hrow[k2];
            unsigned long long h1v = hrow[k2 + 1];
            unsigned long long w0 = *(const unsigned long long*)&Ws2[k2 * 32 + r * 2];
            unsigned long long w1 = *(const unsigned long long*)&Ws2[(k2 + 1) * 32 + r * 2];
            FMA_F32X2(accA, h0, w0);
            FMA_F32X2(accB, h1v, w1);
        }
        float acc = (lo32(accA) + hi32(accA)) + (lo32(accB) + hi32(accB));
        if (L1k) {
            unsigned long long accC = 0ULL, accD = 0ULL;
            const unsigned long long* xrow = (const unsigned long long*)(xs_s + b * HSZ);
#pragma unroll 16
            for (int k2 = 0; k2 < 128; k2 += 2) {
                unsigned long long x0 = xrow[k2];
                unsigned long long x1 = xrow[k2 + 1];
                unsigned long long w0 = *(const unsigned long long*)&Wi2[k2 * 32 + r * 2];
                unsigned long long w1 = *(const unsigned long long*)&Wi2[(k2 + 1) * 32 + r * 2];
                FMA_F32X2(accC, x0, w0);
                FMA_F32X2(accD, x1, w1);
            }
            acc += (lo32(accC) + hi32(accC)) + (lo32(accD) + hi32(accD)) + biasv;
        } else {
            acc += xproj0[((size_t)t * BSZ + b) * G4H + gcol];
        }
        gbuf[b * 17 + r] = acc;
        __syncthreads();

        if (tid < 64) {
            float iv = gbuf[ub * 17 + ujj];
            float fv = gbuf[ub * 17 + 4 + ujj];
            float gv = gbuf[ub * 17 + 8 + ujj];
            float ov = gbuf[ub * 17 + 12 + ujj];
            iv = 1.f / (1.f + expf(-iv));
            fv = 1.f / (1.f + expf(-fv));
            ov = 1.f / (1.f + expf(-ov));
            gv = tanhf(gv);
            c_st = fv * c_st + iv * gv;
            h_st = ov * tanhf(c_st);
            int hcol = j0 + ujj;
            __stcg(&pp[(t + 1) & 1][ub * HSZ + hcol], h_st);
            if (L1k) {
                ah[((size_t)t * BSZ + ub) * HSZ + hcol] = __float2half_rn(h_st);
            } else {
                __stcg(&h1s[((size_t)t * BSZ + ub) * HSZ + hcol], h_st);
            }
        }
        __syncthreads();

        if (tid == 0) {
            unsigned* bar = &bars[L1k ? 1 : 0];
            asm volatile("red.release.gpu.global.add.u32 [%0], 1;" :: "l"(bar) : "memory");
        }
        __syncthreads();
    }

    if (tid < 64) {
        hfin[ub * HSZ + j0 + ujj] = h_st;
        cfin[ub * HSZ + j0 + ujj] = c_st;
    }
}

// ---------------- logits fp16 HMMA (standalone, 2-term split-W) -------------
// 8000 CTAs, 2 CTAs/SM (98816B dyn smem), 2-stage cp.async pipeline.
// Stage s @ s*49152: Ah(16K) Whi(16K) Wlo(16K); bias @ 98304.
#define LOGITS_SMEM 98816
__global__ __launch_bounds__(256, 2) void logits_f16_kernel(
    const __half* __restrict__ ah,
    const __half* __restrict__ Whi, const __half* __restrict__ Wlo,
    const float* __restrict__ bias, float* __restrict__ out)
{
    extern __shared__ float sm[];
    const int tid = threadIdx.x;
    const int my = blockIdx.x / 250, nx = blockIdx.x - my * 250;
    const int m0 = my * 128, n0 = nx * 128;
    const int lane = tid & 31, w = tid >> 5;
    const int wm = w >> 1, wn = w & 1;
    const uint32_t sb = smem_u32(sm);
    float* sbias = sm + 24576;

    if (tid < 128) sbias[tid] = bias[n0 + tid];

    auto issue = [&](int c, int s) {
        uint32_t st = sb + s * 49152;
#pragma unroll
        for (int i = 0; i < 4; i++) {
            int lin = tid + i * 256;
            int row = lin >> 3, ch = lin & 7;
            uint32_t phys = row * 128 + ((ch ^ (row & 7)) << 4);
            size_t ga = (size_t)(m0 + row) * HSZ + c * 64 + ch * 8;
            size_t gb = (size_t)(n0 + row) * HSZ + c * 64 + ch * 8;
            cp16(st + phys,         ah + ga);
            cp16(st + 16384 + phys, Whi + gb);
            cp16(st + 32768 + phys, Wlo + gb);
        }
        asm volatile("cp.async.commit_group;" ::: "memory");
    };

    float d[2][8][4];
#pragma unroll
    for (int mt = 0; mt < 2; mt++)
#pragma unroll
        for (int nt = 0; nt < 8; nt++)
#pragma unroll
            for (int j = 0; j < 4; j++) d[mt][nt][j] = 0.f;

    issue(0, 0);

    for (int c = 0; c < 4; c++) {
        const int s = c & 1;
        if (c < 3) {
            issue(c + 1, s ^ 1);
            asm volatile("cp.async.wait_group 1;" ::: "memory");
        } else {
            asm volatile("cp.async.wait_group 0;" ::: "memory");
        }
        __syncthreads();

        const uint32_t st = sb + s * 49152;
#pragma unroll
        for (int ks = 0; ks < 4; ks++) {
            uint32_t ahf[2][4];
#pragma unroll
            for (int mt = 0; mt < 2; mt++) {
                int row = wm * 32 + mt * 16 + (lane & 7) + ((lane >> 3) & 1) * 8;
                int ch = ks * 2 + ((lane >> 4) & 1);
                ldm_x4(ahf[mt], st + row * 128 + ((ch ^ (row & 7)) << 4));
            }
#pragma unroll
            for (int nt2 = 0; nt2 < 4; nt2++) {
                int row = wn * 64 + nt2 * 16 + (lane & 7) + ((lane >> 4) & 1) * 8;
                int ch = ks * 2 + ((lane >> 3) & 1);
                uint32_t ad = st + 16384 + row * 128 + ((ch ^ (row & 7)) << 4);
                uint32_t qh[4], ql[4];
                ldm_x4(qh, ad);
                ldm_x4(ql, ad + 16384);
#pragma unroll
                for (int mt = 0; mt < 2; mt++) {
                    mma_f16(d[mt][2 * nt2],     ahf[mt], qh);
                    mma_f16(d[mt][2 * nt2],     ahf[mt], ql);
                    mma_f16(d[mt][2 * nt2 + 1], ahf[mt], qh + 2);
                    mma_f16(d[mt][2 * nt2 + 1], ahf[mt], ql + 2);
                }
            }
        }
        __syncthreads();
    }

    // epilogue: bias + [t,b]->[b,t] remapped store
#pragma unroll
    for (int mt = 0; mt < 2; mt++) {
        int mrow = m0 + wm * 32 + mt * 16 + (lane >> 2);
#pragma unroll
        for (int half = 0; half < 2; half++) {
            int m = mrow + half * 8;
            int t = m >> 4, b = m & 15;
            float* dst = out + ((long)b * TSZ + t) * (long)VSZ + n0;
#pragma unroll
            for (int nt = 0; nt < 8; nt++) {
                int lc = wn * 64 + nt * 8 + (lane & 3) * 2;
                float2 v;
                v.x = d[mt][nt][half * 2 + 0] + sbias[lc];
                v.y = d[mt][nt][half * 2 + 1] + sbias[lc + 1];
                *(float2*)(dst + lc) = v;
            }
        }
    }
}

// ---------------- launch ----------------
extern "C" void kernel_launch(void* const* d_in, const int* in_sizes, int n_in,
                              void* d_out, int out_size) {
    const int*   x     = (const int*)d_in[0];
    const float* emb   = (const float*)d_in[1];
    const float* W_ih0 = (const float*)d_in[2];
    const float* W_hh0 = (const float*)d_in[3];
    const float* b_ih0 = (const float*)d_in[4];
    const float* b_hh0 = (const float*)d_in[5];
    const float* W_ih1 = (const float*)d_in[6];
    const float* W_hh1 = (const float*)d_in[7];
    const float* b_ih1 = (const float*)d_in[8];
    const float* b_hh1 = (const float*)d_in[9];
    const float* W_fc  = (const float*)d_in[10];
    const float* b_fc  = (const float*)d_in[11];
    float* out = (float*)d_out;

    float *xp0, *h1s, *hb;
    unsigned* bars;
    __half *whi, *wlo, *ah;
    cudaGetSymbolAddress((void**)&xp0,  g_xproj0);
    cudaGetSymbolAddress((void**)&h1s,  g_h1s);
    cudaGetSymbolAddress((void**)&hb,   g_hbuf);
    cudaGetSymbolAddress((void**)&bars, g_bar);
    cudaGetSymbolAddress((void**)&whi,  g_whi);
    cudaGetSymbolAddress((void**)&wlo,  g_wlo);
    cudaGetSymbolAddress((void**)&ah,   g_ah);

    cudaFuncSetAttribute(fused_lstm_kernel,
                         cudaFuncAttributeMaxDynamicSharedMemorySize, FUSED_SMEM);
    cudaFuncSetAttribute(logits_f16_kernel,
                         cudaFuncAttributeMaxDynamicSharedMemorySize, LOGITS_SMEM);

    const long OFF_H = (long)BSZ * TSZ * VSZ;           // logits size
    const long OFF_C = OFF_H + 2L * BSZ * HSZ;
    const bool ws = ((long)out_size >= OFF_C + 2L * BSZ * HSZ);
    float* hf0 = ws ? out + OFF_H : nullptr;
    float* hf1 = ws ? out + OFF_H + BSZ * HSZ : nullptr;
    float* cf0 = ws ? out + OFF_C : nullptr;
    float* cf1 = ws ? out + OFF_C + BSZ * HSZ : nullptr;
    if (!ws) { hf0 = hb; hf1 = hb; cf0 = hb; cf1 = hb; }

    init_kernel<<<8, 256>>>();
    cvt_splith_kernel<<<2048, 256>>>(W_fc, whi, wlo, VSZ * HSZ / 4);

    dim3 gproj(G4H / 128, MTOT / 128);   // (8, 32)
    sgemm_kernel<0><<<gproj, 256>>>(emb, x, W_ih0, b_ih0, b_hh0, xp0,
                                    MTOT, G4H, ESZ);

    fused_lstm_kernel<<<128, 256, FUSED_SMEM>>>(
        xp0, W_hh0, W_ih1, W_hh1, b_ih1, b_hh1,
        hb, h1s, ah, hf0, cf0, hf1, cf1, bars);

    logits_f16_kernel<<<(VSZ / 128) * (MTOT / 128), 256, LOGITS_SMEM>>>(
        ah, whi, wlo, b_fc, out);
}

// round 17
// speedup vs baseline: 1.7596x; 1.6540x over previous
#include <cuda_runtime.h>
#include <cuda_fp16.h>
#include <cstdint>

// Problem constants  (V, E, H, B, T = 32000, 128, 256, 16, 256)
#define VSZ 32000
#define ESZ 128
#define HSZ 256
#define BSZ 16
#define TSZ 256
#define G4H 1024          // 4*H
#define MTOT 4096         // T*B
#define BH   4096         // B*H

// ---------------- device scratch (no cudaMalloc allowed) ----------------
__device__ float    g_xproj0[MTOT * G4H];   // [T,B,4H]
__device__ unsigned g_bar[2];
// fp16 h exchange planes
__device__ __half g_pph[4 * BH];            // [layer*2+phase][B*H] hi
__device__ __half g_ppl[4 * BH];            // lo
__device__ __half g_h1hi[MTOT * HSZ];       // layer-0 output hi (layer-1 x)
__device__ __half g_h1lo[MTOT * HSZ];
// split-fp16 operands for the HMMA logits GEMM
__device__ __half g_whi[VSZ * HSZ];
__device__ __half g_wlo[VSZ * HSZ];
__device__ __half g_ah [MTOT * HSZ];        // fp16 A written by LSTM layer-1

// ---------------- helpers ----------------
#define FMA_F32X2(acc, a, b) \
    asm("fma.rn.f32x2 %0, %1, %2, %0;" : "+l"(acc) : "l"(a), "l"(b))

__device__ __forceinline__ unsigned long long pack_dup(float v) {
    unsigned long long r;
    asm("mov.b64 %0, {%1, %1};" : "=l"(r) : "f"(v));
    return r;
}
__device__ __forceinline__ unsigned long long pack2(float x, float y) {
    unsigned long long r;
    asm("mov.b64 %0, {%1, %2};" : "=l"(r) : "f"(x), "f"(y));
    return r;
}
__device__ __forceinline__ float lo32(unsigned long long v) {
    return __uint_as_float((unsigned)(v & 0xffffffffULL));
}
__device__ __forceinline__ float hi32(unsigned long long v) {
    return __uint_as_float((unsigned)(v >> 32));
}
__device__ __forceinline__ uint32_t smem_u32(const void* p) {
    uint32_t a;
    asm("{ .reg .u64 t; cvta.to.shared.u64 t, %1; cvt.u32.u64 %0, t; }"
        : "=r"(a) : "l"(p));
    return a;
}
__device__ __forceinline__ void cp16(uint32_t s, const void* g) {
    asm volatile("cp.async.cg.shared.global [%0], [%1], 16;"
                 :: "r"(s), "l"(g) : "memory");
}
__device__ __forceinline__ void ldm_x4(uint32_t* r, uint32_t addr) {
    asm volatile("ldmatrix.sync.aligned.m8n8.x4.shared.b16 {%0,%1,%2,%3}, [%4];"
                 : "=r"(r[0]), "=r"(r[1]), "=r"(r[2]), "=r"(r[3]) : "r"(addr));
}
__device__ __forceinline__ void mma_f16(float* d, const uint32_t* a, const uint32_t* b) {
    asm volatile(
        "mma.sync.aligned.m16n8k16.row.col.f32.f16.f16.f32 "
        "{%0,%1,%2,%3}, {%4,%5,%6,%7}, {%8,%9}, {%0,%1,%2,%3};"
        : "+f"(d[0]), "+f"(d[1]), "+f"(d[2]), "+f"(d[3])
        : "r"(a[0]), "r"(a[1]), "r"(a[2]), "r"(a[3]), "r"(b[0]), "r"(b[1]));
}
__device__ __forceinline__ unsigned ld_acq(const unsigned* p) {
    unsigned v;
    asm volatile("ld.acquire.gpu.global.u32 %0, [%1];" : "=r"(v) : "l"(p));
    return v;
}

// ---------------- init ----------------
__global__ void init_kernel() {
    int tid = blockIdx.x * blockDim.x + threadIdx.x;
    if (tid < 2) g_bar[tid] = 0u;
    unsigned* ph = (unsigned*)g_pph;
    unsigned* pl = (unsigned*)g_ppl;
    for (int i = tid; i < 4 * BH / 2; i += gridDim.x * blockDim.x) {
        ph[i] = 0u;
        pl[i] = 0u;
    }
}

// ---------------- split f32 -> fp16 hi + lo (weights) ----------------
__global__ void cvt_splith_kernel(const float* __restrict__ src,
                                  __half* __restrict__ hi,
                                  __half* __restrict__ lo, int n4) {
    int stride = gridDim.x * blockDim.x;
    const float4* s4 = (const float4*)src;
    unsigned long long* h8 = (unsigned long long*)hi;
    unsigned long long* l8 = (unsigned long long*)lo;
    for (int i = blockIdx.x * blockDim.x + threadIdx.x; i < n4; i += stride) {
        float4 v = s4[i];
        __half h0 = __float2half_rn(v.x);
        __half h1 = __float2half_rn(v.y);
        __half h2 = __float2half_rn(v.z);
        __half h3 = __float2half_rn(v.w);
        __half l0 = __float2half_rn(v.x - __half2float(h0));
        __half l1 = __float2half_rn(v.y - __half2float(h1));
        __half l2 = __float2half_rn(v.z - __half2float(h2));
        __half l3 = __float2half_rn(v.w - __half2float(h3));
        unsigned long long ph =
            (unsigned long long)__half_as_ushort(h0) |
            ((unsigned long long)__half_as_ushort(h1) << 16) |
            ((unsigned long long)__half_as_ushort(h2) << 32) |
            ((unsigned long long)__half_as_ushort(h3) << 48);
        unsigned long long pl =
            (unsigned long long)__half_as_ushort(l0) |
            ((unsigned long long)__half_as_ushort(l1) << 16) |
            ((unsigned long long)__half_as_ushort(l2) << 32) |
            ((unsigned long long)__half_as_ushort(l3) << 48);
        h8[i] = ph;
        l8[i] = pl;
    }
}

// ---------------- SGEMM (x-proj layer 0) ----------------
template <int MODE>
__global__ __launch_bounds__(256) void sgemm_kernel(
    const float* __restrict__ A, const int* __restrict__ gidx,
    const float* __restrict__ Wt, const float* __restrict__ bias1,
    const float* __restrict__ bias2, float* __restrict__ C,
    int M, int N, int K)
{
    __shared__ float As[16][128];
    __shared__ float Bs[16][128];

    const int tid = threadIdx.x;
    const int n0 = blockIdx.x * 128;
    const int m0 = blockIdx.y * 128;

    const int lr = tid >> 2;
    const int lc = (tid & 3) << 2;

    const float* ap0;
    const float* ap1;
    {
        int mA0 = m0 + lr, mA1 = m0 + lr + 64;
        if (MODE == 0) {
            int t0 = mA0 >> 4, b0 = mA0 & 15;
            int t1 = mA1 >> 4, b1 = mA1 & 15;
            ap0 = A + (long)gidx[b0 * TSZ + t0] * K;
            ap1 = A + (long)gidx[b1 * TSZ + t1] * K;
        } else {
            ap0 = A + (long)mA0 * K;
            ap1 = A + (long)mA1 * K;
        }
    }
    const float* bp0 = Wt + (long)(n0 + lr) * K;
    const float* bp1 = Wt + (long)(n0 + lr + 64) * K;

    const int ty = tid >> 4, tx = tid & 15;
    const int row = ty << 3, col = tx << 3;

    unsigned long long acc[8][4];
#pragma unroll
    for (int i = 0; i < 8; i++)
#pragma unroll
        for (int j = 0; j < 4; j++) acc[i][j] = 0ULL;

    for (int kt = 0; kt < K; kt += 16) {
        float4 a0 = *(const float4*)(ap0 + kt + lc);
        float4 a1 = *(const float4*)(ap1 + kt + lc);
        float4 w0 = *(const float4*)(bp0 + kt + lc);
        float4 w1 = *(const float4*)(bp1 + kt + lc);
        __syncthreads();
        As[lc + 0][lr] = a0.x; As[lc + 1][lr] = a0.y;
        As[lc + 2][lr] = a0.z; As[lc + 3][lr] = a0.w;
        As[lc + 0][lr + 64] = a1.x; As[lc + 1][lr + 64] = a1.y;
        As[lc + 2][lr + 64] = a1.z; As[lc + 3][lr + 64] = a1.w;
        Bs[lc + 0][lr] = w0.x; Bs[lc + 1][lr] = w0.y;
        Bs[lc + 2][lr] = w0.z; Bs[lc + 3][lr] = w0.w;
        Bs[lc + 0][lr + 64] = w1.x; Bs[lc + 1][lr + 64] = w1.y;
        Bs[lc + 2][lr + 64] = w1.z; Bs[lc + 3][lr + 64] = w1.w;
        __syncthreads();

#pragma unroll
        for (int k = 0; k < 16; k++) {
            float4 av0 = *(const float4*)&As[k][row];
            float4 av1 = *(const float4*)&As[k][row + 4];
            float4 bq0 = *(const float4*)&Bs[k][col];
            float4 bq1 = *(const float4*)&Bs[k][col + 4];
            unsigned long long bv0 = pack2(bq0.x, bq0.y);
            unsigned long long bv1 = pack2(bq0.z, bq0.w);
            unsigned long long bv2 = pack2(bq1.x, bq1.y);
            unsigned long long bv3 = pack2(bq1.z, bq1.w);
            float av[8] = {av0.x, av0.y, av0.z, av0.w, av1.x, av1.y, av1.z, av1.w};
#pragma unroll
            for (int i = 0; i < 8; i++) {
                unsigned long long a2 = pack_dup(av[i]);
                FMA_F32X2(acc[i][0], a2, bv0);
                FMA_F32X2(acc[i][1], a2, bv1);
                FMA_F32X2(acc[i][2], a2, bv2);
                FMA_F32X2(acc[i][3], a2, bv3);
            }
        }
    }

#pragma unroll
    for (int i = 0; i < 8; i++) {
        int m = m0 + row + i;
        long base = (long)m * N;
#pragma unroll
        for (int j = 0; j < 4; j++) {
            int n = n0 + col + 2 * j;
            float b0 = bias1[n] + (bias2 ? bias2[n] : 0.f);
            float b1 = bias1[n + 1] + (bias2 ? bias2[n + 1] : 0.f);
            C[base + n] = lo32(acc[i][j]) + b0;
            C[base + n + 1] = hi32(acc[i][j]) + b1;
        }
    }
}

// ---------------- fused wavefront 2-layer LSTM, HMMA recurrence ------------
// 128 CTAs. CTA<64: layer 0. CTA>=64: layer 1 (one step behind; on-the-fly
// input projection; emits ah fp16 for logits). Per step, per CTA:
//   D[16b,16r] = h·W_hh^T (+ x·W_ih^T for L1) via 3-term split-fp16 HMMA.
// W planes pre-split into smem (row stride 528B, ldmatrix conflict-free),
// B-fragments preloaded into registers (warp w owns k-steps 2w, 2w+1).
// h exchanged through gmem as fp16 hi/lo planes.
// SMEM bytes: WhhHi@0 WhhLo@8448 WihHi@16896 WihLo@25344
//             hHi@33792 hLo@42240 xHi@50688 xLo@59136
//             pbuf@67584 (float[8][16][18])  gbuf@76800 (float[16][17])
#define FUSED_SMEM 77888
__global__ __launch_bounds__(256, 1) void fused_lstm_kernel(
    const float* __restrict__ xproj0, const float* __restrict__ W_hh0,
    const float* __restrict__ W_ih1, const float* __restrict__ W_hh1,
    const float* __restrict__ b_ih1, const float* __restrict__ b_hh1,
    __half* __restrict__ pph, __half* __restrict__ ppl,
    __half* __restrict__ h1hi, __half* __restrict__ h1lo,
    __half* __restrict__ ah,
    float* __restrict__ hf0, float* __restrict__ cf0,
    float* __restrict__ hf1, float* __restrict__ cf1,
    unsigned* __restrict__ bars)
{
    extern __shared__ char smem[];
    const uint32_t sb = smem_u32(smem);
    const int tid = threadIdx.x;
    const int lane = tid & 31, wid = tid >> 5;
    const bool L1k = (blockIdx.x >= 64);
    const int cta = L1k ? blockIdx.x - 64 : blockIdx.x;
    const int j0 = cta * 4;

    // ---- build split-fp16 W planes in smem ----
    {
        const float* Whh = L1k ? W_hh1 : W_hh0;
        for (int idx = tid; idx < 16 * HSZ; idx += 256) {
            int r = idx >> 8, k = idx & 255;
            int g = r >> 2, jj = r & 3;
            float v = Whh[(g * HSZ + j0 + jj) * HSZ + k];
            __half hh = __float2half_rn(v);
            __half hl = __float2half_rn(v - __half2float(hh));
            *(__half*)(smem + 0    + r * 528 + k * 2) = hh;
            *(__half*)(smem + 8448 + r * 528 + k * 2) = hl;
            if (L1k) {
                float vi = W_ih1[(g * HSZ + j0 + jj) * HSZ + k];
                __half ih = __float2half_rn(vi);
                __half il = __float2half_rn(vi - __half2float(ih));
                *(__half*)(smem + 16896 + r * 528 + k * 2) = ih;
                *(__half*)(smem + 25344 + r * 528 + k * 2) = il;
            }
        }
    }
    __syncthreads();

    // ---- preload B-fragments (W) into registers: warp wid owns ks 2w,2w+1 ----
    const int rowB = (lane & 7) + ((lane >> 4) & 1) * 8;
    const int kbo  = ((lane >> 3) & 1) * 16;
    uint32_t whf[2][4], wlf[2][4], ihf[2][4], ilf[2][4];
#pragma unroll
    for (int s = 0; s < 2; s++) {
        int koff = (wid * 2 + s) * 32 + kbo;
        ldm_x4(whf[s], sb + 0    + rowB * 528 + koff);
        ldm_x4(wlf[s], sb + 8448 + rowB * 528 + koff);
        if (L1k) {
            ldm_x4(ihf[s], sb + 16896 + rowB * 528 + koff);
            ldm_x4(ilf[s], sb + 25344 + rowB * 528 + koff);
        }
    }

    const int b = tid >> 4, r = tid & 15;
    const int gcol = (r >> 2) * HSZ + j0 + (r & 3);
    const int ub = tid >> 2, ujj = tid & 3;
    const float biasv = L1k ? (b_ih1[gcol] + b_hh1[gcol]) : 0.f;

    const int lsel = L1k ? 2 : 0;
    float* pbuf = (float*)(smem + 67584);
    float* gbuf = (float*)(smem + 76800);

    const int rowA = (lane & 7) + ((lane >> 3) & 1) * 8;
    const int kao  = ((lane >> 4) & 1) * 16;

    float c_st = 0.f, h_st = 0.f;

    for (int t = 0; t < TSZ; t++) {
        if (tid == 0) {
            unsigned w0 = L1k ? 64u * (t + 1) : 64u * t;
            while (ld_acq(&bars[0]) < w0) {}
            if (L1k && t > 0) {
                unsigned w1 = 64u * t;
                while (ld_acq(&bars[1]) < w1) {}
            }
        }
        __syncthreads();

        // ---- stage h (and x for L1) fp16 planes into smem ----
        {
            const uint4* sHi = (const uint4*)(pph + (lsel + (t & 1)) * BH);
            const uint4* sLo = (const uint4*)(ppl + (lsel + (t & 1)) * BH);
#pragma unroll
            for (int i = 0; i < 2; i++) {
                int e = tid + i * 256;
                int bb = e >> 5, k8 = e & 31;
                *(uint4*)(smem + 33792 + bb * 528 + k8 * 16) = __ldcg(sHi + e);
                *(uint4*)(smem + 42240 + bb * 528 + k8 * 16) = __ldcg(sLo + e);
            }
            if (L1k) {
                const uint4* xHi = (const uint4*)h1hi + t * 512;
                const uint4* xLo = (const uint4*)h1lo + t * 512;
#pragma unroll
                for (int i = 0; i < 2; i++) {
                    int e = tid + i * 256;
                    int bb = e >> 5, k8 = e & 31;
                    *(uint4*)(smem + 50688 + bb * 528 + k8 * 16) = __ldcg(xHi + e);
                    *(uint4*)(smem + 59136 + bb * 528 + k8 * 16) = __ldcg(xLo + e);
                }
            }
        }
        __syncthreads();

        // ---- HMMA: D[16,16] partial over this warp's 2 k-steps ----
        float d0[4] = {0.f, 0.f, 0.f, 0.f};
        float d1[4] = {0.f, 0.f, 0.f, 0.f};
#pragma unroll
        for (int s = 0; s < 2; s++) {
            int koff = (wid * 2 + s) * 32 + kao;
            uint32_t ahi[4], alo[4];
            ldm_x4(ahi, sb + 33792 + rowA * 528 + koff);
            ldm_x4(alo, sb + 42240 + rowA * 528 + koff);
            mma_f16(d0, ahi, whf[s]);      mma_f16(d1, ahi, whf[s] + 2);
            mma_f16(d0, ahi, wlf[s]);      mma_f16(d1, ahi, wlf[s] + 2);
            mma_f16(d0, alo, whf[s]);      mma_f16(d1, alo, whf[s] + 2);
            if (L1k) {
                uint32_t xhi[4], xlo[4];
                ldm_x4(xhi, sb + 50688 + rowA * 528 + koff);
                ldm_x4(xlo, sb + 59136 + rowA * 528 + koff);
                mma_f16(d0, xhi, ihf[s]);  mma_f16(d1, xhi, ihf[s] + 2);
                mma_f16(d0, xhi, ilf[s]);  mma_f16(d1, xhi, ilf[s] + 2);
                mma_f16(d0, xlo, ihf[s]);  mma_f16(d1, xlo, ihf[s] + 2);
            }
        }
        // partial store: d rows = b (lane>>2, +8), cols = r (nh*8 + (lane&3)*2)
        {
            float* pb = pbuf + wid * 288;
            int br = lane >> 2, cc = (lane & 3) * 2;
            *(float2*)(pb + br * 18 + cc)            = make_float2(d0[0], d0[1]);
            *(float2*)(pb + (br + 8) * 18 + cc)      = make_float2(d0[2], d0[3]);
            *(float2*)(pb + br * 18 + 8 + cc)        = make_float2(d1[0], d1[1]);
            *(float2*)(pb + (br + 8) * 18 + 8 + cc)  = make_float2(d1[2], d1[3]);
        }
        __syncthreads();

        // ---- reduce 8 warps + xproj/bias -> gbuf ----
        {
            float sum = 0.f;
            const float* p0 = pbuf + b * 18 + r;
#pragma unroll
            for (int w = 0; w < 8; w++) sum += p0[w * 288];
            sum += L1k ? biasv : xproj0[((size_t)t * BSZ + b) * G4H + gcol];
            gbuf[b * 17 + r] = sum;
        }
        __syncthreads();

        // ---- gates + h/c update + fp16 h emission ----
        if (tid < 64) {
            float iv = gbuf[ub * 17 + ujj];
            float fv = gbuf[ub * 17 + 4 + ujj];
            float gv = gbuf[ub * 17 + 8 + ujj];
            float ov = gbuf[ub * 17 + 12 + ujj];
            iv = 1.f / (1.f + expf(-iv));
            fv = 1.f / (1.f + expf(-fv));
            ov = 1.f / (1.f + expf(-ov));
            gv = tanhf(gv);
            c_st = fv * c_st + iv * gv;
            h_st = ov * tanhf(c_st);
            int off = ub * HSZ + j0 + ujj;
            __half hh = __float2half_rn(h_st);
            __half hl = __float2half_rn(h_st - __half2float(hh));
            pph[(lsel + ((t + 1) & 1)) * BH + off] = hh;
            ppl[(lsel + ((t + 1) & 1)) * BH + off] = hl;
            if (L1k) {
                ah[(size_t)t * BH + off] = hh;
            } else {
                h1hi[(size_t)t * BH + off] = hh;
                h1lo[(size_t)t * BH + off] = hl;
            }
        }
        __syncthreads();

        if (tid == 0) {
            unsigned* bar = &bars[L1k ? 1 : 0];
            asm volatile("red.release.gpu.global.add.u32 [%0], 1;" :: "l"(bar) : "memory");
        }
        __syncthreads();
    }

    if (tid < 64) {
        float* hfin = L1k ? hf1 : hf0;
        float* cfin = L1k ? cf1 : cf0;
        hfin[ub * HSZ + j0 + ujj] = h_st;
        cfin[ub * HSZ + j0 + ujj] = c_st;
    }
}

// ---------------- logits fp16 HMMA (standalone, 2-term split-W) -------------
#define LOGITS_SMEM 98816
__global__ __launch_bounds__(256, 2) void logits_f16_kernel(
    const __half* __restrict__ ah,
    const __half* __restrict__ Whi, const __half* __restrict__ Wlo,
    const float* __restrict__ bias, float* __restrict__ out)
{
    extern __shared__ float sm[];
    const int tid = threadIdx.x;
    const int my = blockIdx.x / 250, nx = blockIdx.x - my * 250;
    const int m0 = my * 128, n0 = nx * 128;
    const int lane = tid & 31, w = tid >> 5;
    const int wm = w >> 1, wn = w & 1;
    const uint32_t sb = smem_u32(sm);
    float* sbias = sm + 24576;

    if (tid < 128) sbias[tid] = bias[n0 + tid];

    auto issue = [&](int c, int s) {
        uint32_t st = sb + s * 49152;
#pragma unroll
        for (int i = 0; i < 4; i++) {
            int lin = tid + i * 256;
            int row = lin >> 3, ch = lin & 7;
            uint32_t phys = row * 128 + ((ch ^ (row & 7)) << 4);
            size_t ga = (size_t)(m0 + row) * HSZ + c * 64 + ch * 8;
            size_t gb = (size_t)(n0 + row) * HSZ + c * 64 + ch * 8;
            cp16(st + phys,         ah + ga);
            cp16(st + 16384 + phys, Whi + gb);
            cp16(st + 32768 + phys, Wlo + gb);
        }
        asm volatile("cp.async.commit_group;" ::: "memory");
    };

    float d[2][8][4];
#pragma unroll
    for (int mt = 0; mt < 2; mt++)
#pragma unroll
        for (int nt = 0; nt < 8; nt++)
#pragma unroll
            for (int j = 0; j < 4; j++) d[mt][nt][j] = 0.f;

    issue(0, 0);

    for (int c = 0; c < 4; c++) {
        const int s = c & 1;
        if (c < 3) {
            issue(c + 1, s ^ 1);
            asm volatile("cp.async.wait_group 1;" ::: "memory");
        } else {
            asm volatile("cp.async.wait_group 0;" ::: "memory");
        }
        __syncthreads();

        const uint32_t st = sb + s * 49152;
#pragma unroll
        for (int ks = 0; ks < 4; ks++) {
            uint32_t ahf[2][4];
#pragma unroll
            for (int mt = 0; mt < 2; mt++) {
                int row = wm * 32 + mt * 16 + (lane & 7) + ((lane >> 3) & 1) * 8;
                int ch = ks * 2 + ((lane >> 4) & 1);
                ldm_x4(ahf[mt], st + row * 128 + ((ch ^ (row & 7)) << 4));
            }
#pragma unroll
            for (int nt2 = 0; nt2 < 4; nt2++) {
                int row = wn * 64 + nt2 * 16 + (lane & 7) + ((lane >> 4) & 1) * 8;
                int ch = ks * 2 + ((lane >> 3) & 1);
                uint32_t ad = st + 16384 + row * 128 + ((ch ^ (row & 7)) << 4);
                uint32_t qh[4], ql[4];
                ldm_x4(qh, ad);
                ldm_x4(ql, ad + 16384);
#pragma unroll
                for (int mt = 0; mt < 2; mt++) {
                    mma_f16(d[mt][2 * nt2],     ahf[mt], qh);
                    mma_f16(d[mt][2 * nt2],     ahf[mt], ql);
                    mma_f16(d[mt][2 * nt2 + 1], ahf[mt], qh + 2);
                    mma_f16(d[mt][2 * nt2 + 1], ahf[mt], ql + 2);
                }
            }
        }
        __syncthreads();
    }

#pragma unroll
    for (int mt = 0; mt < 2; mt++) {
        int mrow = m0 + wm * 32 + mt * 16 + (lane >> 2);
#pragma unroll
        for (int half = 0; half < 2; half++) {
            int m = mrow + half * 8;
            int t = m >> 4, b = m & 15;
            float* dst = out + ((long)b * TSZ + t) * (long)VSZ + n0;
#pragma unroll
            for (int nt = 0; nt < 8; nt++) {
                int lc = wn * 64 + nt * 8 + (lane & 3) * 2;
                float2 v;
                v.x = d[mt][nt][half * 2 + 0] + sbias[lc];
                v.y = d[mt][nt][half * 2 + 1] + sbias[lc + 1];
                *(float2*)(dst + lc) = v;
            }
        }
    }
}

// ---------------- launch ----------------
extern "C" void kernel_launch(void* const* d_in, const int* in_sizes, int n_in,
                              void* d_out, int out_size) {
    const int*   x     = (const int*)d_in[0];
    const float* emb   = (const float*)d_in[1];
    const float* W_ih0 = (const float*)d_in[2];
    const float* W_hh0 = (const float*)d_in[3];
    const float* b_ih0 = (const float*)d_in[4];
    const float* b_hh0 = (const float*)d_in[5];
    const float* W_ih1 = (const float*)d_in[6];
    const float* W_hh1 = (const float*)d_in[7];
    const float* b_ih1 = (const float*)d_in[8];
    const float* b_hh1 = (const float*)d_in[9];
    const float* W_fc  = (const float*)d_in[10];
    const float* b_fc  = (const float*)d_in[11];
    float* out = (float*)d_out;

    float *xp0;
    unsigned* bars;
    __half *whi, *wlo, *ah, *pph, *ppl, *h1hi, *h1lo;
    cudaGetSymbolAddress((void**)&xp0,  g_xproj0);
    cudaGetSymbolAddress((void**)&bars, g_bar);
    cudaGetSymbolAddress((void**)&whi,  g_whi);
    cudaGetSymbolAddress((void**)&wlo,  g_wlo);
    cudaGetSymbolAddress((void**)&ah,   g_ah);
    cudaGetSymbolAddress((void**)&pph,  g_pph);
    cudaGetSymbolAddress((void**)&ppl,  g_ppl);
    cudaGetSymbolAddress((void**)&h1hi, g_h1hi);
    cudaGetSymbolAddress((void**)&h1lo, g_h1lo);

    cudaFuncSetAttribute(fused_lstm_kernel,
                         cudaFuncAttributeMaxDynamicSharedMemorySize, FUSED_SMEM);
    cudaFuncSetAttribute(logits_f16_kernel,
                         cudaFuncAttributeMaxDynamicSharedMemorySize, LOGITS_SMEM);

    const long OFF_H = (long)BSZ * TSZ * VSZ;           // logits size
    const long OFF_C = OFF_H + 2L * BSZ * HSZ;
    const bool ws = ((long)out_size >= OFF_C + 2L * BSZ * HSZ);
    float* hf0 = ws ? out + OFF_H : nullptr;
    float* hf1 = ws ? out + OFF_H + BSZ * HSZ : nullptr;
    float* cf0 = ws ? out + OFF_C : nullptr;
    float* cf1 = ws ? out + OFF_C + BSZ * HSZ : nullptr;
    if (!ws) { hf0 = xp0; hf1 = xp0; cf0 = xp0; cf1 = xp0; }

    init_kernel<<<8, 256>>>();
    cvt_splith_kernel<<<2048, 256>>>(W_fc, whi, wlo, VSZ * HSZ / 4);

    dim3 gproj(G4H / 128, MTOT / 128);   // (8, 32)
    sgemm_kernel<0><<<gproj, 256>>>(emb, x, W_ih0, b_ih0, b_hh0, xp0,
                                    MTOT, G4H, ESZ);

    fused_lstm_kernel<<<128, 256, FUSED_SMEM>>>(
        xp0, W_hh0, W_ih1, W_hh1, b_ih1, b_hh1,
        pph, ppl, h1hi, h1lo, ah, hf0, cf0, hf1, cf1, bars);

    logits_f16_kernel<<<(VSZ / 128) * (MTOT / 128), 256, LOGITS_SMEM>>>(
        ah, whi, wlo, b_fc, out);
}